// round 16
// baseline (speedup 1.0000x reference)
#include <cuda_runtime.h>
#include <cuda_fp16.h>
#include <math.h>

#define SEQ_L  8192
#define NPAIR  512
#define NBATCH 4
#define FFT_N  16384
#define ROWLEN 1088                 // 1024 + pad
#define SP2(i) ((i) + ((i) >> 4))

// -------- device globals (no cudaMalloc allowed) ----------------------------
__device__ __half2 g_B[(size_t)NBATCH * NPAIR * 16 * 1024];   // 134 MB staging
__device__ __half2 g_kf[(size_t)NPAIR * 16 * 1024];           // 33.5 MB final filter table
__device__ __half2 g_kft[(size_t)NPAIR * 16 * 1024];          // 33.5 MB fp16 intermediate
__device__ float2  g_tw6[64 * 6];                             // {W^j,W^2j,W^3j,W^4j,W^8j,W^12j}, j<64
__constant__ int c_jA[8] = {0, 1, 4, 5, 6, 7, 8, 9};
__constant__ int c_jB[8] = {2, 3, 15, 14, 13, 12, 11, 10};

// ----------------------------- complex helpers ------------------------------
struct C2 { float x, y; };
__device__ __forceinline__ C2 mkc(float a, float b){ C2 r; r.x=a; r.y=b; return r; }
__device__ __forceinline__ C2 cadd(C2 a, C2 b){ return mkc(a.x+b.x, a.y+b.y); }
__device__ __forceinline__ C2 csub(C2 a, C2 b){ return mkc(a.x-b.x, a.y-b.y); }
__device__ __forceinline__ C2 cmul(C2 a, C2 b){ return mkc(a.x*b.x - a.y*b.y, a.x*b.y + a.y*b.x); }
__device__ __forceinline__ C2 cmulc(C2 a, C2 b){ return mkc(a.x*b.x + a.y*b.y, a.y*b.x - a.x*b.y); }
__device__ __forceinline__ C2 mulni(C2 a){ return mkc(a.y, -a.x); }
__device__ __forceinline__ C2 mulpi(C2 a){ return mkc(-a.y, a.x); }

__device__ __forceinline__ C2 w16c(int n) {
    const float C[10] = {1.f, 0.92387953f, 0.70710678f, 0.38268343f, 0.f,
                         -0.38268343f, -0.70710678f, -0.92387953f, -1.f, -0.92387953f};
    const float S[10] = {0.f, -0.38268343f, -0.70710678f, -0.92387953f, -1.f,
                         -0.92387953f, -0.70710678f, -0.38268343f, 0.f, 0.38268343f};
    return mkc(C[n], S[n]);
}
__device__ __forceinline__ C2 twN(int j) {   // W_16384^j
    float sv, cv; sincospif(-(float)j * (1.0f/8192.0f), &sv, &cv); return mkc(cv, sv);
}
// digit-reverse base-4 of 10-bit index (5 digits). Self-inverse.
__device__ __forceinline__ int drev10(int p) {
    unsigned r = __brev((unsigned)p) >> 22;
    return (int)(((r & 0x155u) << 1) | ((r & 0x2AAu) >> 1));
}
// half2 table load -> C2
__device__ __forceinline__ C2 ldk(const __half2* k, int i) {
    float2 t = __half22float2(__ldg(&k[i]));
    return mkc(t.x, t.y);
}

// ---------------- register radix-16 (two fused radix-4 layers) --------------
// table variant: u[0..5] = {u1,u2,u3,u4,u8,u12} preloaded
__device__ __forceinline__ void r16_fwd_u(C2* v, const C2* u) {
    #pragma unroll
    for (int q = 0; q < 4; q++) {
        C2 a=v[q], b=v[q+4], c=v[q+8], d=v[q+12];
        C2 t0=cadd(a,c), t1=csub(a,c), t2=cadd(b,d), t3=mulni(csub(b,d));
        v[q] = cadd(t0,t2);
        C2 o1 = cmul(cadd(t1,t3), u[0]);
        C2 o2 = cmul(csub(t0,t2), u[1]);
        C2 o3 = cmul(csub(t1,t3), u[2]);
        if (q) { o1=cmul(o1,w16c(q)); o2=cmul(o2,w16c(2*q)); o3=cmul(o3,w16c(3*q)); }
        v[q+4]=o1; v[q+8]=o2; v[q+12]=o3;
    }
    #pragma unroll
    for (int s = 0; s < 4; s++) {
        C2 a=v[4*s], b=v[4*s+1], c=v[4*s+2], d=v[4*s+3];
        C2 t0=cadd(a,c), t1=csub(a,c), t2=cadd(b,d), t3=mulni(csub(b,d));
        v[4*s]   = cadd(t0,t2);
        v[4*s+1] = cmul(cadd(t1,t3), u[3]);
        v[4*s+2] = cmul(csub(t0,t2), u[4]);
        v[4*s+3] = cmul(csub(t1,t3), u[5]);
    }
}

__device__ __forceinline__ void r16_inv_u(C2* v, const C2* u) {
    #pragma unroll
    for (int s = 0; s < 4; s++) {
        C2 a = v[4*s];
        C2 b = cmulc(v[4*s+1], u[3]);
        C2 c = cmulc(v[4*s+2], u[4]);
        C2 d = cmulc(v[4*s+3], u[5]);
        C2 p0=cadd(a,c), p1=csub(a,c), p2=cadd(b,d), p3=mulpi(csub(b,d));
        v[4*s]=cadd(p0,p2); v[4*s+1]=cadd(p1,p3); v[4*s+2]=csub(p0,p2); v[4*s+3]=csub(p1,p3);
    }
    #pragma unroll
    for (int q = 0; q < 4; q++) {
        C2 a = v[q];
        C2 b = cmulc(v[q+4],  u[0]);
        C2 c = cmulc(v[q+8],  u[1]);
        C2 d = cmulc(v[q+12], u[2]);
        if (q) { b=cmulc(b,w16c(q)); c=cmulc(c,w16c(2*q)); d=cmulc(d,w16c(3*q)); }
        C2 p0=cadd(a,c), p1=csub(a,c), p2=cadd(b,d), p3=mulpi(csub(b,d));
        v[q]=cadd(p0,p2); v[q+4]=cadd(p1,p3); v[q+8]=csub(p0,p2); v[q+12]=csub(p1,p3);
    }
}

// chain variants (used by kA / kAf / kC where twiddles are per-thread unique)
__device__ __forceinline__ void r16_fwd_zfold(C2* v, C2 u1) {
    C2 u2 = cmul(u1,u1);
    C2 u3 = cmul(u2,u1);
    #pragma unroll
    for (int q = 0; q < 4; q++) {
        C2 a=v[q], b=v[q+4];
        C2 nb = mulni(b);
        C2 o0 = cadd(a,b);
        C2 o1 = cmul(cadd(a,nb), u1);
        C2 o2 = cmul(csub(a,b), u2);
        C2 o3 = cmul(csub(a,nb), u3);
        if (q) { o1=cmul(o1,w16c(q)); o2=cmul(o2,w16c(2*q)); o3=cmul(o3,w16c(3*q)); }
        v[q]=o0; v[q+4]=o1; v[q+8]=o2; v[q+12]=o3;
    }
    C2 u4 = cmul(u2,u2);
    C2 u8 = cmul(u4,u4);
    C2 u12 = cmul(u8,u4);
    #pragma unroll
    for (int s = 0; s < 4; s++) {
        C2 a=v[4*s], b=v[4*s+1], c=v[4*s+2], d=v[4*s+3];
        C2 t0=cadd(a,c), t1=csub(a,c), t2=cadd(b,d), t3=mulni(csub(b,d));
        v[4*s]   = cadd(t0,t2);
        v[4*s+1] = cmul(cadd(t1,t3), u4);
        v[4*s+2] = cmul(csub(t0,t2), u8);
        v[4*s+3] = cmul(csub(t1,t3), u12);
    }
}

__device__ __forceinline__ void r16_inv(C2* v, C2 u1) {
    C2 u2 = cmul(u1,u1);
    C2 u4 = cmul(u2,u2);
    C2 u8 = cmul(u4,u4);
    C2 u12 = cmul(u8,u4);
    #pragma unroll
    for (int s = 0; s < 4; s++) {
        C2 a = v[4*s];
        C2 b = cmulc(v[4*s+1], u4);
        C2 c = cmulc(v[4*s+2], u8);
        C2 d = cmulc(v[4*s+3], u12);
        C2 p0=cadd(a,c), p1=csub(a,c), p2=cadd(b,d), p3=mulpi(csub(b,d));
        v[4*s]=cadd(p0,p2); v[4*s+1]=cadd(p1,p3); v[4*s+2]=csub(p0,p2); v[4*s+3]=csub(p1,p3);
    }
    C2 u3 = cmul(u2,u1);
    #pragma unroll
    for (int q = 0; q < 4; q++) {
        C2 a = v[q];
        C2 b = cmulc(v[q+4],  u1);
        C2 c = cmulc(v[q+8],  u2);
        C2 d = cmulc(v[q+12], u3);
        if (q) { b=cmulc(b,w16c(q)); c=cmulc(c,w16c(2*q)); d=cmulc(d,w16c(3*q)); }
        C2 p0=cadd(a,c), p1=csub(a,c), p2=cadd(b,d), p3=mulpi(csub(b,d));
        v[q]=cadd(p0,p2); v[q+4]=cadd(p1,p3); v[q+8]=csub(p0,p2); v[q+12]=csub(p1,p3);
    }
}

__device__ __forceinline__ void fwd4(C2& a, C2& b, C2& c, C2& d) {
    C2 t0=cadd(a,c), t1=csub(a,c), t2=cadd(b,d), t3=mulni(csub(b,d));
    a=cadd(t0,t2); b=cadd(t1,t3); c=csub(t0,t2); d=csub(t1,t3);
}
__device__ __forceinline__ void inv4(C2& a, C2& b, C2& c, C2& d) {
    C2 p0=cadd(a,c), p1=csub(a,c), p2=cadd(b,d), p3=mulpi(csub(b,d));
    a=cadd(p0,p2); b=cadd(p1,p3); c=csub(p0,p2); d=csub(p1,p3);
}

// pointwise packed-real product: A=Z[f], Braw=Z[N-f], Cv=Zk[f], Draw=Zk[N-f]
__device__ __forceinline__ void pw(C2 A, C2 Braw, C2 Cv, C2 Draw, C2& outF, C2& outNF) {
    const float s = 1.0f / (4.0f * (float)FFT_N);
    float br = Braw.x, bi = -Braw.y;
    float dr = Draw.x, di = -Draw.y;
    float apbr = A.x + br, apbi = A.y + bi;
    float ambr = A.x - br, ambi = A.y - bi;
    float cpdr = Cv.x + dr, cpdi = Cv.y + di;
    float cmdr = Cv.x - dr, cmdi = Cv.y - di;
    float Pr = apbr * cpdr - apbi * cpdi, Pi = apbr * cpdi + apbi * cpdr;
    float Qr = ambr * cmdr - ambi * cmdi, Qi = ambr * cmdi + ambi * cmdr;
    outF  = mkc((Pr + Qi) * s,  (Pi - Qr) * s);
    outNF = mkc((Pr - Qi) * s, -(Pi + Qr) * s);
}

// --------------------- 1024-point row passes in smem ------------------------
__device__ __forceinline__ C2 lds(const float2* s, int i){ float2 t = s[SP2(i)]; return mkc(t.x,t.y); }
__device__ __forceinline__ void sts(float2* s, int i, C2 v){ s[SP2(i)] = make_float2(v.x,v.y); }

__device__ __forceinline__ void row_fwd(float2* s, int bf, int LM) {
    const int m = 1 << LM;
    const int r = bf & (m - 1);
    const int i0 = ((bf >> LM) << (LM + 4)) + r;
    const int j = r << (6 - LM);
    C2 u[6];
    #pragma unroll
    for (int q = 0; q < 6; q++) { float2 t = __ldg(&g_tw6[6*j + q]); u[q] = mkc(t.x, t.y); }
    C2 v[16];
    #pragma unroll
    for (int jj = 0; jj < 16; jj++) v[jj] = lds(s, i0 + jj*m);
    r16_fwd_u(v, u);
    #pragma unroll
    for (int jj = 0; jj < 16; jj++) sts(s, i0 + jj*m, v[jj]);
}
__device__ __forceinline__ void row_inv(float2* s, int bf, int LM) {
    const int m = 1 << LM;
    const int r = bf & (m - 1);
    const int i0 = ((bf >> LM) << (LM + 4)) + r;
    const int j = r << (6 - LM);
    C2 u[6];
    #pragma unroll
    for (int q = 0; q < 6; q++) { float2 t = __ldg(&g_tw6[6*j + q]); u[q] = mkc(t.x, t.y); }
    C2 v[16];
    #pragma unroll
    for (int jj = 0; jj < 16; jj++) v[jj] = lds(s, i0 + jj*m);
    r16_inv_u(v, u);
    #pragma unroll
    for (int jj = 0; jj < 16; jj++) sts(s, i0 + jj*m, v[jj]);
}

// ---------------- kA: x -> first 16-pt stage -> g_B (batched transpose) -----
__global__ void __launch_bounds__(1024) kA(const float2* __restrict__ x2) {
    __shared__ __half2 tile[8][32][33];
    const int tx = threadIdx.x & 31, ty = threadIdx.x >> 5;
    const int b = blockIdx.z;
    const int pr0 = blockIdx.x * 32, n20 = blockIdx.y * 32;
    const float2* xb = x2 + (size_t)b * SEQ_L * NPAIR;
    const int n2 = n20 + ty;
    C2 v[16];
    #pragma unroll
    for (int j = 0; j < 8; j++) {
        float2 t = __ldg(&xb[(size_t)(j * 1024 + n2) * NPAIR + pr0 + tx]);
        v[j] = mkc(t.x, t.y);
    }
    r16_fwd_zfold(v, twN(n2));
    #pragma unroll
    for (int h = 0; h < 2; h++) {
        __syncthreads();
        #pragma unroll
        for (int jj = 0; jj < 8; jj++)
            tile[jj][ty][tx] = __floats2half2_rn(v[8*h + jj].x, v[8*h + jj].y);
        __syncthreads();
        #pragma unroll
        for (int jj = 0; jj < 8; jj++)
            g_B[((size_t)(b * NPAIR + pr0 + ty) * 16 + 8*h + jj) * 1024 + n20 + tx] =
                tile[jj][tx][ty];
    }
}

// ------- kAf: filt -> first stage -> g_kft; block 0 also fills g_tw6 --------
__global__ void __launch_bounds__(1024) kAf(const float* __restrict__ filt) {
    if (blockIdx.x == 0 && threadIdx.x < 64) {
        const int j = threadIdx.x;
        const int pows[6] = {1, 2, 3, 4, 8, 12};
        #pragma unroll
        for (int q = 0; q < 6; q++) {
            float sv, cv;
            sincospif(-(float)(pows[q] * j) * (1.0f / 512.0f), &sv, &cv);
            g_tw6[6*j + q] = make_float2(cv, sv);
        }
    }
    const int n2 = threadIdx.x, pr = blockIdx.x;
    const float* k0 = filt + (size_t)(2 * pr) * SEQ_L;
    const float* k1 = k0 + SEQ_L;
    C2 v[16];
    #pragma unroll
    for (int j = 0; j < 8; j++) {
        int t = j * 1024 + n2;
        v[j] = mkc(k0[t], k1[t]);
    }
    r16_fwd_zfold(v, twN(n2));
    #pragma unroll
    for (int j = 0; j < 16; j++)
        g_kft[((size_t)pr * 16 + j) * 1024 + n2] = __floats2half2_rn(v[j].x, v[j].y);
}

// ------ kBf: forward 1024-FFT of filter rows, g_kft(fp16) -> g_kf(fp16) -----
__global__ void __launch_bounds__(128) kBf() {
    __shared__ float2 s0[ROWLEN], s1[ROWLEN];
    const int t = threadIdx.x;
    const int pr = blockIdx.y, j0 = blockIdx.x * 2;
    const __half2* r0 = g_kft + ((size_t)pr * 16 + j0) * 1024;
    const __half2* r1 = r0 + 1024;
    __half2* o0 = g_kf + ((size_t)pr * 16 + j0) * 1024;
    __half2* o1 = o0 + 1024;
    for (int i = t; i < 1024; i += 128) {
        s0[SP2(i)] = __half22float2(r0[i]);
        s1[SP2(i)] = __half22float2(r1[i]);
    }
    __syncthreads();
    float2* srow = (t >= 64) ? s1 : s0;
    const int bf = t & 63;
    row_fwd(srow, bf, 6); __syncthreads();
    row_fwd(srow, bf, 2); __syncthreads();
    for (int idx = t; idx < 512; idx += 128) {
        float2* s = (idx & 256) ? s1 : s0;
        __half2* o = (idx & 256) ? o1 : o0;
        int g = idx & 255;
        C2 a = lds(s,4*g), b = lds(s,4*g+1), c = lds(s,4*g+2), d = lds(s,4*g+3);
        fwd4(a, b, c, d);
        o[4*g]   = __floats2half2_rn(a.x, a.y);
        o[4*g+1] = __floats2half2_rn(b.x, b.y);
        o[4*g+2] = __floats2half2_rn(c.x, c.y);
        o[4*g+3] = __floats2half2_rn(d.x, d.y);
    }
}

// ---------------- kB: row FFT + pointwise + row inverse ---------------------
__global__ void __launch_bounds__(128, 9) kB() {
    __shared__ float2 s0[ROWLEN], s1[ROWLEN];
    const int t = threadIdx.x;
    const int b = blockIdx.x & 3, pi = blockIdx.x >> 2, pr = blockIdx.y;
    const int jA = c_jA[pi], jB = c_jB[pi];
    __half2* rA = g_B + ((size_t)(b * NPAIR + pr) * 16 + jA) * 1024;
    __half2* rB = g_B + ((size_t)(b * NPAIR + pr) * 16 + jB) * 1024;
    const __half2* kfA = g_kf + ((size_t)pr * 16 + jA) * 1024;
    const __half2* kfB = g_kf + ((size_t)pr * 16 + jB) * 1024;
    // vectorized load: 2 half2 per 8B transaction
    const float2* rA2 = (const float2*)rA;
    const float2* rB2 = (const float2*)rB;
    for (int i = t; i < 512; i += 128) {
        float2 pa = rA2[i];
        __half2 h0 = *(__half2*)&pa.x, h1 = *(__half2*)&pa.y;
        s0[SP2(2*i)]   = __half22float2(h0);
        s0[SP2(2*i+1)] = __half22float2(h1);
        float2 pb = rB2[i];
        __half2 g0 = *(__half2*)&pb.x, g1 = *(__half2*)&pb.y;
        s1[SP2(2*i)]   = __half22float2(g0);
        s1[SP2(2*i+1)] = __half22float2(g1);
    }
    __syncthreads();
    float2* srow = (t >= 64) ? s1 : s0;
    const int bf = t & 63;
    row_fwd(srow, bf, 6); __syncthreads();
    row_fwd(srow, bf, 2); __syncthreads();

    if (pi) {
        // cross pair: row A pos p  <->  row B pos 1023-p
        #pragma unroll
        for (int gi = 0; gi < 2; gi++) {
            int g = t + gi * 128, g2 = 255 - g;
            C2 a[4], bb[4], ka[4], kb[4];
            #pragma unroll
            for (int s = 0; s < 4; s++) a[s] = lds(s0, 4*g + s);
            fwd4(a[0], a[1], a[2], a[3]);
            #pragma unroll
            for (int s = 0; s < 4; s++) bb[s] = lds(s1, 4*g2 + s);
            fwd4(bb[0], bb[1], bb[2], bb[3]);
            #pragma unroll
            for (int s = 0; s < 4; s++) {
                ka[s] = ldk(kfA, 4*g + s);
                kb[s] = ldk(kfB, 4*g2 + s);
            }
            #pragma unroll
            for (int s = 0; s < 4; s++) pw(a[s], bb[3-s], ka[s], kb[3-s], a[s], bb[3-s]);
            inv4(a[0], a[1], a[2], a[3]);
            inv4(bb[0], bb[1], bb[2], bb[3]);
            #pragma unroll
            for (int s = 0; s < 4; s++) { sts(s0, 4*g + s, a[s]); sts(s1, 4*g2 + s, bb[s]); }
        }
    } else {
        // row s1 = k1=8: self-mirrored, p <-> 1023-p within the row
        {
            int g = t, g2 = 255 - t;
            C2 a[4], bb[4], ka[4], kb[4];
            #pragma unroll
            for (int s = 0; s < 4; s++) a[s] = lds(s1, 4*g + s);
            fwd4(a[0], a[1], a[2], a[3]);
            #pragma unroll
            for (int s = 0; s < 4; s++) bb[s] = lds(s1, 4*g2 + s);
            fwd4(bb[0], bb[1], bb[2], bb[3]);
            #pragma unroll
            for (int s = 0; s < 4; s++) {
                ka[s] = ldk(kfB, 4*g + s);
                kb[s] = ldk(kfB, 4*g2 + s);
            }
            #pragma unroll
            for (int s = 0; s < 4; s++) pw(a[s], bb[3-s], ka[s], kb[3-s], a[s], bb[3-s]);
            inv4(a[0], a[1], a[2], a[3]);
            inv4(bb[0], bb[1], bb[2], bb[3]);
            #pragma unroll
            for (int s = 0; s < 4; s++) { sts(s1, 4*g + s, a[s]); sts(s1, 4*g2 + s, bb[s]); }
        }
        // row s0 = k1=0: complete forward, frequency-indexed pairing, inverse
        for (int g = t; g < 256; g += 128) {
            C2 a = lds(s0,4*g), b2 = lds(s0,4*g+1), c = lds(s0,4*g+2), d = lds(s0,4*g+3);
            fwd4(a, b2, c, d);
            sts(s0,4*g,a); sts(s0,4*g+1,b2); sts(s0,4*g+2,c); sts(s0,4*g+3,d);
        }
        __syncthreads();
        for (int k2 = t; k2 <= 512; k2 += 128) {
            int p  = drev10(k2);
            int p2 = drev10((1024 - k2) & 1023);
            C2 A = lds(s0, p);
            C2 Cv = ldk(kfA, p);
            if (k2 == 0 || k2 == 512) {
                C2 o, dm; pw(A, A, Cv, Cv, o, dm); sts(s0, p, o);
            } else {
                C2 Bv = lds(s0, p2);
                C2 Dv = ldk(kfA, p2);
                C2 oF, oN; pw(A, Bv, Cv, Dv, oF, oN);
                sts(s0, p, oF); sts(s0, p2, oN);
            }
        }
        __syncthreads();
        for (int g = t; g < 256; g += 128) {
            C2 a = lds(s0,4*g), b2 = lds(s0,4*g+1), c = lds(s0,4*g+2), d = lds(s0,4*g+3);
            inv4(a, b2, c, d);
            sts(s0,4*g,a); sts(s0,4*g+1,b2); sts(s0,4*g+2,c); sts(s0,4*g+3,d);
        }
    }
    __syncthreads();
    row_inv(srow, bf, 2); __syncthreads();
    row_inv(srow, bf, 6); __syncthreads();
    // vectorized store: 2 half2 per 8B transaction
    float2* wA2 = (float2*)rA;
    float2* wB2 = (float2*)rB;
    for (int i = t; i < 512; i += 128) {
        float2 a0 = s0[SP2(2*i)], a1 = s0[SP2(2*i+1)];
        float2 oa;
        *(__half2*)&oa.x = __floats2half2_rn(a0.x, a0.y);
        *(__half2*)&oa.y = __floats2half2_rn(a1.x, a1.y);
        wA2[i] = oa;
        float2 b0 = s1[SP2(2*i)], b1 = s1[SP2(2*i+1)];
        float2 ob;
        *(__half2*)&ob.x = __floats2half2_rn(b0.x, b0.y);
        *(__half2*)&ob.y = __floats2half2_rn(b1.x, b1.y);
        wB2[i] = ob;
    }
}

// ---------------- kC: 16-pt inverse stage -> y (batched transpose) ----------
__global__ void __launch_bounds__(1024) kC(float2* __restrict__ y2) {
    __shared__ float2 tile[4][32][33];
    const int tx = threadIdx.x & 31, ty = threadIdx.x >> 5;
    const int b = blockIdx.z;
    const int pr0 = blockIdx.x * 32, n20 = blockIdx.y * 32;
    const int n2 = n20 + tx, pr = pr0 + ty;
    C2 v[16];
    #pragma unroll
    for (int j = 0; j < 16; j++) {
        float2 a = __half22float2(g_B[((size_t)(b * NPAIR + pr) * 16 + j) * 1024 + n2]);
        v[j] = mkc(a.x, a.y);
    }
    r16_inv(v, twN(n2));
    float2* yb = y2 + (size_t)b * SEQ_L * NPAIR;
    #pragma unroll
    for (int h = 0; h < 2; h++) {
        __syncthreads();
        #pragma unroll
        for (int jj = 0; jj < 4; jj++)
            tile[jj][ty][tx] = make_float2(v[4*h + jj].x, v[4*h + jj].y);
        __syncthreads();
        #pragma unroll
        for (int jj = 0; jj < 4; jj++)
            yb[(size_t)((4*h + jj) * 1024 + n20 + ty) * NPAIR + pr0 + tx] = tile[jj][tx][ty];
    }
}

// ------------------------------ launch --------------------------------------
extern "C" void kernel_launch(void* const* d_in, const int* in_sizes, int n_in,
                              void* d_out, int out_size) {
    const float* x    = (const float*)d_in[0];
    const float* filt = (const float*)d_in[1];
    if (n_in >= 2 && in_sizes[0] == 2 * NPAIR * SEQ_L &&
        in_sizes[1] == NBATCH * SEQ_L * 2 * NPAIR) {
        const float* t = x; x = filt; filt = t;
    }
    float* out = (float*)d_out;

    kAf<<<NPAIR, 1024>>>(filt);
    kBf<<<dim3(8, NPAIR), 128>>>();
    kA<<<dim3(16, 32, NBATCH), 1024>>>((const float2*)x);
    kB<<<dim3(32, NPAIR), 128>>>();
    kC<<<dim3(16, 32, NBATCH), 1024>>>((float2*)out);
}

// round 17
// speedup vs baseline: 1.0819x; 1.0819x over previous
#include <cuda_runtime.h>
#include <cuda_fp16.h>
#include <math.h>

#define SEQ_L  8192
#define NPAIR  512
#define NBATCH 4
#define FFT_N  16384
#define ROWLEN 1088                 // 1024 + pad
#define SP2(i) ((i) + ((i) >> 4))

// -------- device globals (no cudaMalloc allowed) ----------------------------
__device__ __half2 g_B[(size_t)NBATCH * NPAIR * 16 * 1024];   // 134 MB staging
__device__ __half2 g_kf[(size_t)NPAIR * 16 * 1024];           // 33.5 MB final filter table
__device__ __half2 g_kft[(size_t)NPAIR * 16 * 1024];          // 33.5 MB fp16 intermediate
__constant__ int c_jA[8] = {0, 1, 4, 5, 6, 7, 8, 9};
__constant__ int c_jB[8] = {2, 3, 15, 14, 13, 12, 11, 10};

// ----------------------------- complex helpers ------------------------------
struct C2 { float x, y; };
__device__ __forceinline__ C2 mkc(float a, float b){ C2 r; r.x=a; r.y=b; return r; }
__device__ __forceinline__ C2 cadd(C2 a, C2 b){ return mkc(a.x+b.x, a.y+b.y); }
__device__ __forceinline__ C2 csub(C2 a, C2 b){ return mkc(a.x-b.x, a.y-b.y); }
__device__ __forceinline__ C2 cmul(C2 a, C2 b){ return mkc(a.x*b.x - a.y*b.y, a.x*b.y + a.y*b.x); }
__device__ __forceinline__ C2 cmulc(C2 a, C2 b){ return mkc(a.x*b.x + a.y*b.y, a.y*b.x - a.x*b.y); }
__device__ __forceinline__ C2 mulni(C2 a){ return mkc(a.y, -a.x); }
__device__ __forceinline__ C2 mulpi(C2 a){ return mkc(-a.y, a.x); }

__device__ __forceinline__ C2 w16c(int n) {
    const float C[10] = {1.f, 0.92387953f, 0.70710678f, 0.38268343f, 0.f,
                         -0.38268343f, -0.70710678f, -0.92387953f, -1.f, -0.92387953f};
    const float S[10] = {0.f, -0.38268343f, -0.70710678f, -0.92387953f, -1.f,
                         -0.92387953f, -0.70710678f, -0.38268343f, 0.f, 0.38268343f};
    return mkc(C[n], S[n]);
}
__device__ __forceinline__ C2 twN(int j) {   // W_16384^j
    float sv, cv; sincospif(-(float)j * (1.0f/8192.0f), &sv, &cv); return mkc(cv, sv);
}
__device__ __forceinline__ C2 tw1k(int j) {  // W_1024^j
    float sv, cv; sincospif(-(float)j * (1.0f/512.0f), &sv, &cv); return mkc(cv, sv);
}
// digit-reverse base-4 of 10-bit index (5 digits). Self-inverse.
__device__ __forceinline__ int drev10(int p) {
    unsigned r = __brev((unsigned)p) >> 22;
    return (int)(((r & 0x155u) << 1) | ((r & 0x2AAu) >> 1));
}
// half2 table load -> C2
__device__ __forceinline__ C2 ldk(const __half2* k, int i) {
    float2 t = __half22float2(__ldg(&k[i]));
    return mkc(t.x, t.y);
}
// vectorized: load kf[i..i+3] (16B aligned) as one LDG.128 into 4 C2
__device__ __forceinline__ void ldk4(const __half2* k, int i, C2* out) {
    float4 q = __ldg((const float4*)(k + i));
    float2 t0 = __half22float2(*(__half2*)&q.x);
    float2 t1 = __half22float2(*(__half2*)&q.y);
    float2 t2 = __half22float2(*(__half2*)&q.z);
    float2 t3 = __half22float2(*(__half2*)&q.w);
    out[0] = mkc(t0.x, t0.y);
    out[1] = mkc(t1.x, t1.y);
    out[2] = mkc(t2.x, t2.y);
    out[3] = mkc(t3.x, t3.y);
}

// ---------------- register radix-16 (two fused radix-4 layers) --------------
__device__ __forceinline__ void r16_fwd(C2* v, C2 u1) {
    C2 u2 = cmul(u1,u1);
    C2 u3 = cmul(u2,u1);
    #pragma unroll
    for (int q = 0; q < 4; q++) {
        C2 a=v[q], b=v[q+4], c=v[q+8], d=v[q+12];
        C2 t0=cadd(a,c), t1=csub(a,c), t2=cadd(b,d), t3=mulni(csub(b,d));
        v[q] = cadd(t0,t2);
        C2 o1 = cmul(cadd(t1,t3), u1);
        C2 o2 = cmul(csub(t0,t2), u2);
        C2 o3 = cmul(csub(t1,t3), u3);
        if (q) { o1=cmul(o1,w16c(q)); o2=cmul(o2,w16c(2*q)); o3=cmul(o3,w16c(3*q)); }
        v[q+4]=o1; v[q+8]=o2; v[q+12]=o3;
    }
    C2 u4 = cmul(u2,u2);
    C2 u8 = cmul(u4,u4);
    C2 u12 = cmul(u8,u4);
    #pragma unroll
    for (int s = 0; s < 4; s++) {
        C2 a=v[4*s], b=v[4*s+1], c=v[4*s+2], d=v[4*s+3];
        C2 t0=cadd(a,c), t1=csub(a,c), t2=cadd(b,d), t3=mulni(csub(b,d));
        v[4*s]   = cadd(t0,t2);
        v[4*s+1] = cmul(cadd(t1,t3), u4);
        v[4*s+2] = cmul(csub(t0,t2), u8);
        v[4*s+3] = cmul(csub(t1,t3), u12);
    }
}

__device__ __forceinline__ void r16_fwd_zfold(C2* v, C2 u1) {
    C2 u2 = cmul(u1,u1);
    C2 u3 = cmul(u2,u1);
    #pragma unroll
    for (int q = 0; q < 4; q++) {
        C2 a=v[q], b=v[q+4];
        C2 nb = mulni(b);
        C2 o0 = cadd(a,b);
        C2 o1 = cmul(cadd(a,nb), u1);
        C2 o2 = cmul(csub(a,b), u2);
        C2 o3 = cmul(csub(a,nb), u3);
        if (q) { o1=cmul(o1,w16c(q)); o2=cmul(o2,w16c(2*q)); o3=cmul(o3,w16c(3*q)); }
        v[q]=o0; v[q+4]=o1; v[q+8]=o2; v[q+12]=o3;
    }
    C2 u4 = cmul(u2,u2);
    C2 u8 = cmul(u4,u4);
    C2 u12 = cmul(u8,u4);
    #pragma unroll
    for (int s = 0; s < 4; s++) {
        C2 a=v[4*s], b=v[4*s+1], c=v[4*s+2], d=v[4*s+3];
        C2 t0=cadd(a,c), t1=csub(a,c), t2=cadd(b,d), t3=mulni(csub(b,d));
        v[4*s]   = cadd(t0,t2);
        v[4*s+1] = cmul(cadd(t1,t3), u4);
        v[4*s+2] = cmul(csub(t0,t2), u8);
        v[4*s+3] = cmul(csub(t1,t3), u12);
    }
}

__device__ __forceinline__ void r16_inv(C2* v, C2 u1) {
    C2 u2 = cmul(u1,u1);
    C2 u4 = cmul(u2,u2);
    C2 u8 = cmul(u4,u4);
    C2 u12 = cmul(u8,u4);
    #pragma unroll
    for (int s = 0; s < 4; s++) {
        C2 a = v[4*s];
        C2 b = cmulc(v[4*s+1], u4);
        C2 c = cmulc(v[4*s+2], u8);
        C2 d = cmulc(v[4*s+3], u12);
        C2 p0=cadd(a,c), p1=csub(a,c), p2=cadd(b,d), p3=mulpi(csub(b,d));
        v[4*s]=cadd(p0,p2); v[4*s+1]=cadd(p1,p3); v[4*s+2]=csub(p0,p2); v[4*s+3]=csub(p1,p3);
    }
    C2 u3 = cmul(u2,u1);
    #pragma unroll
    for (int q = 0; q < 4; q++) {
        C2 a = v[q];
        C2 b = cmulc(v[q+4],  u1);
        C2 c = cmulc(v[q+8],  u2);
        C2 d = cmulc(v[q+12], u3);
        if (q) { b=cmulc(b,w16c(q)); c=cmulc(c,w16c(2*q)); d=cmulc(d,w16c(3*q)); }
        C2 p0=cadd(a,c), p1=csub(a,c), p2=cadd(b,d), p3=mulpi(csub(b,d));
        v[q]=cadd(p0,p2); v[q+4]=cadd(p1,p3); v[q+8]=csub(p0,p2); v[q+12]=csub(p1,p3);
    }
}

__device__ __forceinline__ void fwd4(C2& a, C2& b, C2& c, C2& d) {
    C2 t0=cadd(a,c), t1=csub(a,c), t2=cadd(b,d), t3=mulni(csub(b,d));
    a=cadd(t0,t2); b=cadd(t1,t3); c=csub(t0,t2); d=csub(t1,t3);
}
__device__ __forceinline__ void inv4(C2& a, C2& b, C2& c, C2& d) {
    C2 p0=cadd(a,c), p1=csub(a,c), p2=cadd(b,d), p3=mulpi(csub(b,d));
    a=cadd(p0,p2); b=cadd(p1,p3); c=csub(p0,p2); d=csub(p1,p3);
}

// pointwise packed-real product: A=Z[f], Braw=Z[N-f], Cv=Zk[f], Draw=Zk[N-f]
__device__ __forceinline__ void pw(C2 A, C2 Braw, C2 Cv, C2 Draw, C2& outF, C2& outNF) {
    const float s = 1.0f / (4.0f * (float)FFT_N);
    float br = Braw.x, bi = -Braw.y;
    float dr = Draw.x, di = -Draw.y;
    float apbr = A.x + br, apbi = A.y + bi;
    float ambr = A.x - br, ambi = A.y - bi;
    float cpdr = Cv.x + dr, cpdi = Cv.y + di;
    float cmdr = Cv.x - dr, cmdi = Cv.y - di;
    float Pr = apbr * cpdr - apbi * cpdi, Pi = apbr * cpdi + apbi * cpdr;
    float Qr = ambr * cmdr - ambi * cmdi, Qi = ambr * cmdi + ambi * cmdr;
    outF  = mkc((Pr + Qi) * s,  (Pi - Qr) * s);
    outNF = mkc((Pr - Qi) * s, -(Pi + Qr) * s);
}

// --------------------- 1024-point row passes in smem ------------------------
__device__ __forceinline__ C2 lds(const float2* s, int i){ float2 t = s[SP2(i)]; return mkc(t.x,t.y); }
__device__ __forceinline__ void sts(float2* s, int i, C2 v){ s[SP2(i)] = make_float2(v.x,v.y); }

__device__ __forceinline__ void row_fwd(float2* s, int bf, int LM) {
    const int m = 1 << LM;
    const int r = bf & (m - 1);
    const int i0 = ((bf >> LM) << (LM + 4)) + r;
    C2 u1 = tw1k(r << (6 - LM));
    C2 v[16];
    #pragma unroll
    for (int j = 0; j < 16; j++) v[j] = lds(s, i0 + j*m);
    r16_fwd(v, u1);
    #pragma unroll
    for (int j = 0; j < 16; j++) sts(s, i0 + j*m, v[j]);
}
__device__ __forceinline__ void row_inv(float2* s, int bf, int LM) {
    const int m = 1 << LM;
    const int r = bf & (m - 1);
    const int i0 = ((bf >> LM) << (LM + 4)) + r;
    C2 u1 = tw1k(r << (6 - LM));
    C2 v[16];
    #pragma unroll
    for (int j = 0; j < 16; j++) v[j] = lds(s, i0 + j*m);
    r16_inv(v, u1);
    #pragma unroll
    for (int j = 0; j < 16; j++) sts(s, i0 + j*m, v[j]);
}

// ---------------- kA: x -> first 16-pt stage -> g_B (batched transpose) -----
__global__ void __launch_bounds__(1024) kA(const float2* __restrict__ x2) {
    __shared__ __half2 tile[8][32][33];
    const int tx = threadIdx.x & 31, ty = threadIdx.x >> 5;
    const int b = blockIdx.z;
    const int pr0 = blockIdx.x * 32, n20 = blockIdx.y * 32;
    const float2* xb = x2 + (size_t)b * SEQ_L * NPAIR;
    const int n2 = n20 + ty;
    C2 v[16];
    #pragma unroll
    for (int j = 0; j < 8; j++) {
        float2 t = __ldg(&xb[(size_t)(j * 1024 + n2) * NPAIR + pr0 + tx]);
        v[j] = mkc(t.x, t.y);
    }
    r16_fwd_zfold(v, twN(n2));
    #pragma unroll
    for (int h = 0; h < 2; h++) {
        __syncthreads();
        #pragma unroll
        for (int jj = 0; jj < 8; jj++)
            tile[jj][ty][tx] = __floats2half2_rn(v[8*h + jj].x, v[8*h + jj].y);
        __syncthreads();
        #pragma unroll
        for (int jj = 0; jj < 8; jj++)
            g_B[((size_t)(b * NPAIR + pr0 + ty) * 16 + 8*h + jj) * 1024 + n20 + tx] =
                tile[jj][tx][ty];
    }
}

// ------- kAf: filt -> first stage -> g_kft (fp16 intermediate) --------------
__global__ void __launch_bounds__(1024) kAf(const float* __restrict__ filt) {
    const int n2 = threadIdx.x, pr = blockIdx.x;
    const float* k0 = filt + (size_t)(2 * pr) * SEQ_L;
    const float* k1 = k0 + SEQ_L;
    C2 v[16];
    #pragma unroll
    for (int j = 0; j < 8; j++) {
        int t = j * 1024 + n2;
        v[j] = mkc(k0[t], k1[t]);
    }
    r16_fwd_zfold(v, twN(n2));
    #pragma unroll
    for (int j = 0; j < 16; j++)
        g_kft[((size_t)pr * 16 + j) * 1024 + n2] = __floats2half2_rn(v[j].x, v[j].y);
}

// ------ kBf: forward 1024-FFT of filter rows, g_kft(fp16) -> g_kf(fp16) -----
__global__ void __launch_bounds__(128) kBf() {
    __shared__ float2 s0[ROWLEN], s1[ROWLEN];
    const int t = threadIdx.x;
    const int pr = blockIdx.y, j0 = blockIdx.x * 2;
    const __half2* r0 = g_kft + ((size_t)pr * 16 + j0) * 1024;
    const __half2* r1 = r0 + 1024;
    __half2* o0 = g_kf + ((size_t)pr * 16 + j0) * 1024;
    __half2* o1 = o0 + 1024;
    for (int i = t; i < 1024; i += 128) {
        s0[SP2(i)] = __half22float2(r0[i]);
        s1[SP2(i)] = __half22float2(r1[i]);
    }
    __syncthreads();
    float2* srow = (t >= 64) ? s1 : s0;
    const int bf = t & 63;
    row_fwd(srow, bf, 6); __syncthreads();
    row_fwd(srow, bf, 2); __syncthreads();
    for (int idx = t; idx < 512; idx += 128) {
        float2* s = (idx & 256) ? s1 : s0;
        __half2* o = (idx & 256) ? o1 : o0;
        int g = idx & 255;
        C2 a = lds(s,4*g), b = lds(s,4*g+1), c = lds(s,4*g+2), d = lds(s,4*g+3);
        fwd4(a, b, c, d);
        o[4*g]   = __floats2half2_rn(a.x, a.y);
        o[4*g+1] = __floats2half2_rn(b.x, b.y);
        o[4*g+2] = __floats2half2_rn(c.x, c.y);
        o[4*g+3] = __floats2half2_rn(d.x, d.y);
    }
}

// ---------------- kB: row FFT + pointwise + row inverse ---------------------
__global__ void __launch_bounds__(128, 9) kB() {
    __shared__ float2 s0[ROWLEN], s1[ROWLEN];
    const int t = threadIdx.x;
    const int b = blockIdx.x & 3, pi = blockIdx.x >> 2, pr = blockIdx.y;
    const int jA = c_jA[pi], jB = c_jB[pi];
    __half2* rA = g_B + ((size_t)(b * NPAIR + pr) * 16 + jA) * 1024;
    __half2* rB = g_B + ((size_t)(b * NPAIR + pr) * 16 + jB) * 1024;
    const __half2* kfA = g_kf + ((size_t)pr * 16 + jA) * 1024;
    const __half2* kfB = g_kf + ((size_t)pr * 16 + jB) * 1024;
    // vectorized load: 2 half2 per 8B transaction
    const float2* rA2 = (const float2*)rA;
    const float2* rB2 = (const float2*)rB;
    for (int i = t; i < 512; i += 128) {
        float2 pa = rA2[i];
        __half2 h0 = *(__half2*)&pa.x, h1 = *(__half2*)&pa.y;
        s0[SP2(2*i)]   = __half22float2(h0);
        s0[SP2(2*i+1)] = __half22float2(h1);
        float2 pb = rB2[i];
        __half2 g0 = *(__half2*)&pb.x, g1 = *(__half2*)&pb.y;
        s1[SP2(2*i)]   = __half22float2(g0);
        s1[SP2(2*i+1)] = __half22float2(g1);
    }
    __syncthreads();
    float2* srow = (t >= 64) ? s1 : s0;
    const int bf = t & 63;
    row_fwd(srow, bf, 6); __syncthreads();
    row_fwd(srow, bf, 2); __syncthreads();

    if (pi) {
        // cross pair: row A pos p  <->  row B pos 1023-p
        #pragma unroll
        for (int gi = 0; gi < 2; gi++) {
            int g = t + gi * 128, g2 = 255 - g;
            C2 a[4], bb[4], ka[4], kb[4];
            #pragma unroll
            for (int s = 0; s < 4; s++) a[s] = lds(s0, 4*g + s);
            fwd4(a[0], a[1], a[2], a[3]);
            #pragma unroll
            for (int s = 0; s < 4; s++) bb[s] = lds(s1, 4*g2 + s);
            fwd4(bb[0], bb[1], bb[2], bb[3]);
            ldk4(kfA, 4*g,  ka);
            ldk4(kfB, 4*g2, kb);
            #pragma unroll
            for (int s = 0; s < 4; s++) pw(a[s], bb[3-s], ka[s], kb[3-s], a[s], bb[3-s]);
            inv4(a[0], a[1], a[2], a[3]);
            inv4(bb[0], bb[1], bb[2], bb[3]);
            #pragma unroll
            for (int s = 0; s < 4; s++) { sts(s0, 4*g + s, a[s]); sts(s1, 4*g2 + s, bb[s]); }
        }
    } else {
        // row s1 = k1=8: self-mirrored, p <-> 1023-p within the row
        {
            int g = t, g2 = 255 - t;
            C2 a[4], bb[4], ka[4], kb[4];
            #pragma unroll
            for (int s = 0; s < 4; s++) a[s] = lds(s1, 4*g + s);
            fwd4(a[0], a[1], a[2], a[3]);
            #pragma unroll
            for (int s = 0; s < 4; s++) bb[s] = lds(s1, 4*g2 + s);
            fwd4(bb[0], bb[1], bb[2], bb[3]);
            ldk4(kfB, 4*g,  ka);
            ldk4(kfB, 4*g2, kb);
            #pragma unroll
            for (int s = 0; s < 4; s++) pw(a[s], bb[3-s], ka[s], kb[3-s], a[s], bb[3-s]);
            inv4(a[0], a[1], a[2], a[3]);
            inv4(bb[0], bb[1], bb[2], bb[3]);
            #pragma unroll
            for (int s = 0; s < 4; s++) { sts(s1, 4*g + s, a[s]); sts(s1, 4*g2 + s, bb[s]); }
        }
        // row s0 = k1=0: complete forward, frequency-indexed pairing, inverse
        for (int g = t; g < 256; g += 128) {
            C2 a = lds(s0,4*g), b2 = lds(s0,4*g+1), c = lds(s0,4*g+2), d = lds(s0,4*g+3);
            fwd4(a, b2, c, d);
            sts(s0,4*g,a); sts(s0,4*g+1,b2); sts(s0,4*g+2,c); sts(s0,4*g+3,d);
        }
        __syncthreads();
        for (int k2 = t; k2 <= 512; k2 += 128) {
            int p  = drev10(k2);
            int p2 = drev10((1024 - k2) & 1023);
            C2 A = lds(s0, p);
            C2 Cv = ldk(kfA, p);
            if (k2 == 0 || k2 == 512) {
                C2 o, dm; pw(A, A, Cv, Cv, o, dm); sts(s0, p, o);
            } else {
                C2 Bv = lds(s0, p2);
                C2 Dv = ldk(kfA, p2);
                C2 oF, oN; pw(A, Bv, Cv, Dv, oF, oN);
                sts(s0, p, oF); sts(s0, p2, oN);
            }
        }
        __syncthreads();
        for (int g = t; g < 256; g += 128) {
            C2 a = lds(s0,4*g), b2 = lds(s0,4*g+1), c = lds(s0,4*g+2), d = lds(s0,4*g+3);
            inv4(a, b2, c, d);
            sts(s0,4*g,a); sts(s0,4*g+1,b2); sts(s0,4*g+2,c); sts(s0,4*g+3,d);
        }
    }
    __syncthreads();
    row_inv(srow, bf, 2); __syncthreads();
    row_inv(srow, bf, 6); __syncthreads();
    // vectorized store: 2 half2 per 8B transaction
    float2* wA2 = (float2*)rA;
    float2* wB2 = (float2*)rB;
    for (int i = t; i < 512; i += 128) {
        float2 a0 = s0[SP2(2*i)], a1 = s0[SP2(2*i+1)];
        float2 oa;
        *(__half2*)&oa.x = __floats2half2_rn(a0.x, a0.y);
        *(__half2*)&oa.y = __floats2half2_rn(a1.x, a1.y);
        wA2[i] = oa;
        float2 b0 = s1[SP2(2*i)], b1 = s1[SP2(2*i+1)];
        float2 ob;
        *(__half2*)&ob.x = __floats2half2_rn(b0.x, b0.y);
        *(__half2*)&ob.y = __floats2half2_rn(b1.x, b1.y);
        wB2[i] = ob;
    }
}

// ---------------- kC: 16-pt inverse stage -> y (batched transpose) ----------
__global__ void __launch_bounds__(1024) kC(float2* __restrict__ y2) {
    __shared__ float2 tile[4][32][33];
    const int tx = threadIdx.x & 31, ty = threadIdx.x >> 5;
    const int b = blockIdx.z;
    const int pr0 = blockIdx.x * 32, n20 = blockIdx.y * 32;
    const int n2 = n20 + tx, pr = pr0 + ty;
    C2 v[16];
    #pragma unroll
    for (int j = 0; j < 16; j++) {
        float2 a = __half22float2(g_B[((size_t)(b * NPAIR + pr) * 16 + j) * 1024 + n2]);
        v[j] = mkc(a.x, a.y);
    }
    r16_inv(v, twN(n2));
    float2* yb = y2 + (size_t)b * SEQ_L * NPAIR;
    #pragma unroll
    for (int h = 0; h < 2; h++) {
        __syncthreads();
        #pragma unroll
        for (int jj = 0; jj < 4; jj++)
            tile[jj][ty][tx] = make_float2(v[4*h + jj].x, v[4*h + jj].y);
        __syncthreads();
        #pragma unroll
        for (int jj = 0; jj < 4; jj++)
            yb[(size_t)((4*h + jj) * 1024 + n20 + ty) * NPAIR + pr0 + tx] = tile[jj][tx][ty];
    }
}

// ------------------------------ launch --------------------------------------
extern "C" void kernel_launch(void* const* d_in, const int* in_sizes, int n_in,
                              void* d_out, int out_size) {
    const float* x    = (const float*)d_in[0];
    const float* filt = (const float*)d_in[1];
    if (n_in >= 2 && in_sizes[0] == 2 * NPAIR * SEQ_L &&
        in_sizes[1] == NBATCH * SEQ_L * 2 * NPAIR) {
        const float* t = x; x = filt; filt = t;
    }
    float* out = (float*)d_out;

    kAf<<<NPAIR, 1024>>>(filt);
    kBf<<<dim3(8, NPAIR), 128>>>();
    kA<<<dim3(16, 32, NBATCH), 1024>>>((const float2*)x);
    kB<<<dim3(32, NPAIR), 128>>>();
    kC<<<dim3(16, 32, NBATCH), 1024>>>((float2*)out);
}